// round 10
// baseline (speedup 1.0000x reference)
#include <cuda_runtime.h>
#include <cuda_fp16.h>
#include <math.h>
#include <stdint.h>

// Problem constants
#define F 18
#define PP 128
#define HH 256
#define NCLS 625
#define NTOK (F*PP)            // 2304
#define NELEM (F*PP*HH)        // 589824
#define TOTROWS 22016          // 17*256 + 15*512 + 13*768
#define ROFF0 0
#define ROFF1 4352
#define ROFF2 12032
#define TPAIRS 1152            // NTOK/2

// -------- device scratch (allocation-free) --------
__device__ float d_inputs[NELEM];          // fp32 inputs (for halt)
__device__ __half d_Xh[NELEM];             // fp16 inputs (for QKV mma)
__device__ __half d_Qh[3*NELEM];
__device__ __half d_Kh[3*NELEM];
__device__ uint32_t d_Vt[3*8*32*TPAIRS];   // [si][h][dim][tokpair] packed half2
__device__ __half d_attnh[TOTROWS*HH];     // attention output (fp16)
__device__ __half d_Wqkvh[9*HH*HH];        // QKV weights transposed [si*3+which][n][k] fp16
__device__ __half d_Woh[3*HH*HH];          // Wo transposed [si][n][k] fp16
__device__ float d_oall[TOTROWS*HH];
__device__ float d_context[NELEM];
__device__ float d_sig[NTOK];
__device__ float d_ptn[F];
__device__ float d_Rt[F];
__device__ float d_w[F];
__device__ float d_partial[F*HH];

__device__ __forceinline__ uint32_t packh2(float a, float b) {
    __half2 h = __floats2half2_rn(a, b);
    return *(uint32_t*)&h;
}

__device__ __forceinline__ uint32_t h2ex2(uint32_t x) {
    uint32_t y;
    asm("ex2.approx.f16x2 %0, %1;" : "=r"(y) : "r"(x));
    return y;
}

// mma.sync m16n8k16 fp16 -> fp32 accumulate in-place
__device__ __forceinline__ void mma_f16(float c[4], const uint32_t a[4],
                                        uint32_t b0, uint32_t b1)
{
    asm volatile(
        "mma.sync.aligned.m16n8k16.row.col.f32.f16.f16.f32 "
        "{%0,%1,%2,%3}, {%4,%5,%6,%7}, {%8,%9}, {%0,%1,%2,%3};\n"
        : "+f"(c[0]), "+f"(c[1]), "+f"(c[2]), "+f"(c[3])
        : "r"(a[0]), "r"(a[1]), "r"(a[2]), "r"(a[3]), "r"(b0), "r"(b1));
}

// =================== halting: phase 1, two positions per warp (MLP=4) ===================
__global__ void __launch_bounds__(256)
halt_sig_k(const float* __restrict__ x, const float* __restrict__ hW,
           const float* __restrict__ hb, float* __restrict__ sig)
{
    int warp = threadIdx.x >> 5;
    int lane = threadIdx.x & 31;
    int pos = blockIdx.x * 8 + warp;      // [0, 1152); second position = pos + 1152
    const float* xp0 = x + (size_t)pos * HH + lane * 8;
    const float* xp1 = x + (size_t)(pos + TPAIRS) * HH + lane * 8;
    const float* wp = hW + lane * 8;
    float4 a0 = *(const float4*)xp0;
    float4 a1 = *(const float4*)(xp0 + 4);
    float4 b0 = *(const float4*)xp1;
    float4 b1 = *(const float4*)(xp1 + 4);
    float4 w0 = *(const float4*)wp;
    float4 w1 = *(const float4*)(wp + 4);
    float acc0 = a0.x * w0.x + a0.y * w0.y + a0.z * w0.z + a0.w * w0.w
               + a1.x * w1.x + a1.y * w1.y + a1.z * w1.z + a1.w * w1.w;
    float acc1 = b0.x * w0.x + b0.y * w0.y + b0.z * w0.z + b0.w * w0.w
               + b1.x * w1.x + b1.y * w1.y + b1.z * w1.z + b1.w * w1.w;
    #pragma unroll
    for (int off = 16; off > 0; off >>= 1) {
        acc0 += __shfl_xor_sync(0xffffffffu, acc0, off);
        acc1 += __shfl_xor_sync(0xffffffffu, acc1, off);
    }
    if (lane == 0) {
        sig[pos] = 1.f / (1.f + __expf(-(acc0 + hb[0])));
        sig[pos + TPAIRS] = 1.f / (1.f + __expf(-(acc1 + hb[0])));
    }
}

// =================== halting phase 2 (mean) + ACT, one block ===================
__global__ void __launch_bounds__(576)
act2_k(const float* __restrict__ sig, float* __restrict__ ptn,
       float* __restrict__ Rt, float* __restrict__ w, int first)
{
    int f = threadIdx.x >> 5;      // 0..17
    int lane = threadIdx.x & 31;
    const float4 v = *(const float4*)&sig[f * PP + lane * 4];
    float acc = v.x + v.y + v.z + v.w;
    #pragma unroll
    for (int off = 16; off > 0; off >>= 1)
        acc += __shfl_xor_sync(0xffffffffu, acc, off);
    if (lane == 0) {
        float pf = acc * (1.f / 128.f);
        float pt = first ? 0.f : ptn[f];
        float rt = first ? 0.f : Rt[f];
        float run = (pt < 1.0f) ? 1.f : 0.f;
        float t = pt + pf * run;
        float nh   = (t > 0.99f)  ? run : 0.f;
        float run2 = (t <= 0.99f) ? run : 0.f;
        pt = pt + pf * run2;
        rt = rt + nh * (1.f - pt);
        pt = pt + nh * rt;
        ptn[f] = pt; Rt[f] = rt;
        w[f] = pf * run2 + nh * rt;
    }
}

// =================== weight transpose+convert: [k][n] f32 -> [n][k] f16 ===================
__global__ void __launch_bounds__(256)
convwt_k(const float* __restrict__ W, __half* __restrict__ Wt)
{
    __shared__ float t[32][33];
    int z = blockIdx.z;
    int k0 = blockIdx.x * 32, n0 = blockIdx.y * 32;
    int tx = threadIdx.x, ty = threadIdx.y;     // 32 x 8
    const float* src = W + (size_t)z * HH * HH;
    __half* dst = Wt + (size_t)z * HH * HH;
    #pragma unroll
    for (int r = ty; r < 32; r += 8)
        t[r][tx] = src[(size_t)(k0 + r) * HH + n0 + tx];
    __syncthreads();
    #pragma unroll
    for (int r = ty; r < 32; r += 8)
        dst[(size_t)(n0 + r) * HH + k0 + tx] = __float2half(t[tx][r]);
}

__global__ void __launch_bounds__(256)
convwt_qkv_k(const float* __restrict__ Wq, const float* __restrict__ Wk,
             const float* __restrict__ Wv, __half* __restrict__ Wt)
{
    __shared__ float t[32][33];
    int z = blockIdx.z;              // 0..8
    int si = z / 3, which = z - si * 3;
    const float* W = (which == 0) ? Wq : ((which == 1) ? Wk : Wv);
    const float* src = W + (size_t)si * HH * HH;
    __half* dst = Wt + (size_t)z * HH * HH;
    int k0 = blockIdx.x * 32, n0 = blockIdx.y * 32;
    int tx = threadIdx.x, ty = threadIdx.y;
    #pragma unroll
    for (int r = ty; r < 32; r += 8)
        t[r][tx] = src[(size_t)(k0 + r) * HH + n0 + tx];
    __syncthreads();
    #pragma unroll
    for (int r = ty; r < 32; r += 8)
        dst[(size_t)(n0 + r) * HH + k0 + tx] = __float2half(t[tx][r]);
}

// =================== X -> fp16 ===================
__global__ void xconv_k(const float* __restrict__ X, __half* __restrict__ Xh)
{
    int i = blockIdx.x * 256 + threadIdx.x;
    float2 v = *(const float2*)&X[2 * i];
    *(uint32_t*)&Xh[2 * i] = packh2(v.x, v.y);
}

// =================== fp16 mma GEMM mainloop, tile 128x128, K=256 ===================
#define OSTRIDE 36
__device__ __forceinline__ void mma_mainloop(const __half* __restrict__ A, int bm,
                                             const __half* __restrict__ Bw, int bn,
                                             uint32_t* sbuf, float acc[2][8][4])
{
    uint32_t* As = sbuf;
    uint32_t* Bs = sbuf + 128 * OSTRIDE;
    const int tid  = threadIdx.x;
    const int warp = tid >> 5;
    const int lane = tid & 31;
    const int gid  = lane >> 2;
    const int tig  = lane & 3;
    const int wm = (warp & 3) * 32;
    const int wn = (warp >> 2) * 64;

    #pragma unroll
    for (int mt = 0; mt < 2; mt++)
        #pragma unroll
        for (int nt = 0; nt < 8; nt++)
            #pragma unroll
            for (int i = 0; i < 4; i++) acc[mt][nt][i] = 0.f;

    for (int kc = 0; kc < 256; kc += 64) {
        __syncthreads();
        #pragma unroll
        for (int i = tid; i < 1024; i += 256) {
            int m = i >> 3, q = i & 7;
            uint4 v = *(const uint4*)&A[(size_t)(bm + m) * 256 + kc + q * 8];
            uint32_t* dst = &As[m * OSTRIDE + q * 4];
            dst[0] = v.x; dst[1] = v.y; dst[2] = v.z; dst[3] = v.w;
        }
        #pragma unroll
        for (int i = tid; i < 1024; i += 256) {
            int n = i >> 3, q = i & 7;
            uint4 v = *(const uint4*)&Bw[(size_t)(bn + n) * 256 + kc + q * 8];
            uint32_t* dst = &Bs[n * OSTRIDE + q * 4];
            dst[0] = v.x; dst[1] = v.y; dst[2] = v.z; dst[3] = v.w;
        }
        __syncthreads();
        #pragma unroll
        for (int ks = 0; ks < 4; ks++) {
            uint32_t a[2][4];
            #pragma unroll
            for (int mt = 0; mt < 2; mt++) {
                int r0 = (wm + mt * 16 + gid) * OSTRIDE + ks * 8;
                int r1 = (wm + mt * 16 + gid + 8) * OSTRIDE + ks * 8;
                a[mt][0] = As[r0 + tig];
                a[mt][1] = As[r1 + tig];
                a[mt][2] = As[r0 + tig + 4];
                a[mt][3] = As[r1 + tig + 4];
            }
            #pragma unroll
            for (int nt = 0; nt < 8; nt++) {
                int nr = (wn + nt * 8 + gid) * OSTRIDE + ks * 8;
                uint32_t b0 = Bs[nr + tig];
                uint32_t b1 = Bs[nr + tig + 4];
                #pragma unroll
                for (int mt = 0; mt < 2; mt++)
                    mma_f16(acc[mt][nt], a[mt], b0, b1);
            }
        }
    }
}

// QKV mma GEMM: grid (18, 2, 9); z: si=z/3, which=z%3.
// which<2 -> fp16 Q/K (Q prescaled). which==2 -> V written directly to the
// transposed packed Vt layout via an smem restage (vtrans fused away).
__global__ void __launch_bounds__(256)
gemm_qkv_mma_k(const __half* __restrict__ Xh, const __half* __restrict__ Wt,
               const float* __restrict__ bq, const float* __restrict__ bk,
               const float* __restrict__ bv,
               __half* __restrict__ Q, __half* __restrict__ K,
               uint32_t* __restrict__ Vt)
{
    __shared__ uint32_t sbuf[2 * 128 * OSTRIDE];
    int z = blockIdx.z;
    int si = z / 3, which = z - si * 3;
    int bm = blockIdx.x * 128, bn = blockIdx.y * 128;

    float acc[2][8][4];
    mma_mainloop(Xh, bm, Wt + (size_t)z * HH * HH, bn, sbuf, acc);

    const int tid  = threadIdx.x;
    const int warp = tid >> 5;
    const int lane = tid & 31;
    const int gid  = lane >> 2;
    const int tig  = lane & 3;
    const int wm = (warp & 3) * 32;
    const int wn = (warp >> 2) * 64;

    if (which < 2) {
        const float* bias = ((which == 0) ? bq : bk) + si * HH;
        __half* C = ((which == 0) ? Q : K) + (size_t)si * NELEM;
        float oscale = (which == 0) ? (0.17677669529663687f * 1.4426950408889634f) : 1.0f;
        #pragma unroll
        for (int nt = 0; nt < 8; nt++) {
            int n = bn + wn + nt * 8 + 2 * tig;
            float b0 = bias[n], b1 = bias[n + 1];
            #pragma unroll
            for (int mt = 0; mt < 2; mt++) {
                int m = bm + wm + mt * 16 + gid;
                *(uint32_t*)&C[(size_t)m * 256 + n] =
                    packh2((acc[mt][nt][0] + b0) * oscale, (acc[mt][nt][1] + b1) * oscale);
                *(uint32_t*)&C[(size_t)(m + 8) * 256 + n] =
                    packh2((acc[mt][nt][2] + b0) * oscale, (acc[mt][nt][3] + b1) * oscale);
            }
        }
    } else {
        // stage fp16 tile [tok][dim] in smem, then write transposed packed Vt
        const float* bias = bv + si * HH;
        __half* stag = (__half*)sbuf;            // [128 tok][stride 130]
        __syncthreads();                          // mainloop smem reads done
        #pragma unroll
        for (int nt = 0; nt < 8; nt++) {
            int nl = wn + nt * 8 + 2 * tig;
            float b0 = bias[bn + nl], b1 = bias[bn + nl + 1];
            #pragma unroll
            for (int mt = 0; mt < 2; mt++) {
                int ml = wm + mt * 16 + gid;
                *(uint32_t*)&stag[ml * 130 + nl] =
                    packh2(acc[mt][nt][0] + b0, acc[mt][nt][1] + b1);
                *(uint32_t*)&stag[(ml + 8) * 130 + nl] =
                    packh2(acc[mt][nt][2] + b0, acc[mt][nt][3] + b1);
            }
        }
        __syncthreads();
        const int tpg0 = bm >> 1;
        uint32_t* vtb = Vt + (size_t)si * 8 * 32 * TPAIRS;
        #pragma unroll
        for (int j = tid; j < 8192; j += 256) {
            int tp = j & 63;          // local token pair
            int nl = j >> 6;          // local dim col 0..127
            int ncol = bn + nl;
            int h = ncol >> 5, d = ncol & 31;
            __half lo = stag[(2 * tp) * 130 + nl];
            __half hi = stag[(2 * tp + 1) * 130 + nl];
            __half2 pr = __halves2half2(lo, hi);
            vtb[((size_t)(h * 32 + d)) * TPAIRS + tpg0 + tp] = *(uint32_t*)&pr;
        }
    }
}

// O-projection mma GEMM: grid (172, 2)
__global__ void __launch_bounds__(256)
gemm_oproj_mma_k(const __half* __restrict__ A, const __half* __restrict__ Wt,
                 const float* __restrict__ bo, float* __restrict__ C)
{
    __shared__ uint32_t sbuf[2 * 128 * OSTRIDE];
    int bm = blockIdx.x * 128, bn = blockIdx.y * 128;
    int si = (bm >= ROFF2) ? 2 : ((bm >= ROFF1) ? 1 : 0);

    float acc[2][8][4];
    mma_mainloop(A, bm, Wt + (size_t)si * HH * HH, bn, sbuf, acc);

    const int tid  = threadIdx.x;
    const int warp = tid >> 5;
    const int lane = tid & 31;
    const int gid  = lane >> 2;
    const int tig  = lane & 3;
    const int wm = (warp & 3) * 32;
    const int wn = (warp >> 2) * 64;
    const float* bias = bo + si * HH;

    #pragma unroll
    for (int nt = 0; nt < 8; nt++) {
        int n = bn + wn + nt * 8 + 2 * tig;
        float b0 = bias[n], b1 = bias[n + 1];
        #pragma unroll
        for (int mt = 0; mt < 2; mt++) {
            int m = bm + wm + mt * 16 + gid;
            *(float2*)&C[(size_t)m * 256 + n] =
                make_float2(acc[mt][nt][0] + b0, acc[mt][nt][1] + b1);
            *(float2*)&C[(size_t)(m + 8) * 256 + n] =
                make_float2(acc[mt][nt][2] + b0, acc[mt][nt][3] + b1);
        }
    }
}

// =================== tensor-core flash attention, hd=32, all fp16 mma ===================
// Logits tiny -> no max tracking. Exponentials in fp16 (ex2.approx.f16x2) on the
// pre-packed logits: halves MUFU ops and the ex2 output IS the PV A-fragment.
// block = 256 threads (8 warps) = 128 queries of one (scale, window, head).
#define KPSTRIDE 36
#define VTSTRIDE 36
__global__ void __launch_bounds__(256, 3)
attn_mma_k(const __half* __restrict__ Qg, const __half* __restrict__ Kg,
           const uint32_t* __restrict__ Vt, __half* __restrict__ O)
{
    __shared__ uint32_t Kp[64 * KPSTRIDE];   // [key][kpair]
    __shared__ uint32_t Vs[32 * VTSTRIDE];   // [dim][keypair]

    const int tid  = threadIdx.x;
    const int warp = tid >> 5;
    const int lane = tid & 31;
    const int gid  = lane >> 2;
    const int tig  = lane & 3;
    const int h    = blockIdx.y;

    int pid = blockIdx.x;
    int si, S, w, j0, rowoff;
    if (pid < 34)      { si = 0; S = 256; w = pid >> 1; j0 = (pid & 1) << 7; rowoff = ROFF0; }
    else if (pid < 94) { pid -= 34; si = 1; S = 512; w = pid >> 2; j0 = (pid & 3) << 7; rowoff = ROFF1; }
    else               { pid -= 94; si = 2; S = 768; w = pid / 6;  j0 = (pid - w * 6) << 7; rowoff = ROFF2; }

    const __half* Q = Qg + (size_t)si * NELEM;
    const __half* K = Kg + (size_t)si * NELEM;
    const uint32_t* Vtb = Vt + ((size_t)si * 8 + h) * 32 * TPAIRS;

    const int qrow = w * PP + j0 + warp * 16 + gid;
    uint32_t qa[2][4];
    #pragma unroll
    for (int ks = 0; ks < 2; ks++) {
        const uint32_t* q0 = (const uint32_t*)(Q + (size_t)qrow * HH + h * 32 + ks * 16);
        const uint32_t* q1 = (const uint32_t*)(Q + (size_t)(qrow + 8) * HH + h * 32 + ks * 16);
        qa[ks][0] = q0[tig];
        qa[ks][1] = q1[tig];
        qa[ks][2] = q0[tig + 4];
        qa[ks][3] = q1[tig + 4];
    }

    float o[4][4];
    #pragma unroll
    for (int v = 0; v < 4; v++)
        #pragma unroll
        for (int i = 0; i < 4; i++) o[v][i] = 0.f;
    float l0 = 0.f, l1 = 0.f;

    for (int kb = 0; kb < S; kb += 64) {
        __syncthreads();
        {
            const uint32_t* kg = (const uint32_t*)(K + ((size_t)(w * PP + kb)) * HH + h * 32);
            #pragma unroll
            for (int i = tid; i < 1024; i += 256) {
                int key = i >> 4, kp = i & 15;
                Kp[key * KPSTRIDE + kp] = kg[(size_t)key * (HH / 2) + kp];
            }
        }
        {
            const uint32_t* vg = Vtb + ((w * PP + kb) >> 1);
            #pragma unroll
            for (int i = tid; i < 1024; i += 256) {
                int d = i >> 5, kp = i & 31;
                Vs[d * VTSTRIDE + kp] = vg[(size_t)d * TPAIRS + kp];
            }
        }
        __syncthreads();

        float s[8][4];
        #pragma unroll
        for (int t = 0; t < 8; t++) {
            s[t][0] = s[t][1] = s[t][2] = s[t][3] = 0.f;
            const int krow = (8 * t + gid) * KPSTRIDE;
            #pragma unroll
            for (int ks = 0; ks < 2; ks++) {
                uint32_t b0 = Kp[krow + ks * 8 + tig];
                uint32_t b1 = Kp[krow + ks * 8 + tig + 4];
                mma_f16(s[t], qa[ks], b0, b1);
            }
        }

        // pack logits to fp16, exponentiate in fp16 (log2 domain), sum in fp32
        uint32_t e0[8], e1[8];
        #pragma unroll
        for (int t = 0; t < 8; t++) {
            e0[t] = h2ex2(packh2(s[t][0], s[t][1]));   // row gid
            e1[t] = h2ex2(packh2(s[t][2], s[t][3]));   // row gid+8
            float2 f0 = __half22float2(*(__half2*)&e0[t]);
            float2 f1 = __half22float2(*(__half2*)&e1[t]);
            l0 += f0.x + f0.y;
            l1 += f1.x + f1.y;
        }

        #pragma unroll
        for (int u = 0; u < 4; u++) {
            uint32_t pa[4];
            pa[0] = e0[2*u];
            pa[1] = e1[2*u];
            pa[2] = e0[2*u+1];
            pa[3] = e1[2*u+1];
            #pragma unroll
            for (int v = 0; v < 4; v++) {
                uint32_t b0 = Vs[(gid + 8 * v) * VTSTRIDE + 8 * u + tig];
                uint32_t b1 = Vs[(gid + 8 * v) * VTSTRIDE + 8 * u + tig + 4];
                mma_f16(o[v], pa, b0, b1);
            }
        }
    }

    l0 += __shfl_xor_sync(0xffffffffu, l0, 1);
    l0 += __shfl_xor_sync(0xffffffffu, l0, 2);
    l1 += __shfl_xor_sync(0xffffffffu, l1, 1);
    l1 += __shfl_xor_sync(0xffffffffu, l1, 2);
    float il0 = 1.f / l0, il1 = 1.f / l1;

    const int orow = rowoff + w * S + j0 + warp * 16 + gid;
    #pragma unroll
    for (int v = 0; v < 4; v++) {
        *(uint32_t*)&O[(size_t)orow * HH + h * 32 + v * 8 + 2 * tig] =
            packh2(o[v][0] * il0, o[v][1] * il0);
        *(uint32_t*)&O[(size_t)(orow + 8) * HH + h * 32 + v * 8 + 2 * tig] =
            packh2(o[v][2] * il1, o[v][3] * il1);
    }
}

// =================== fused overlap-add gather (3 scales) + finalize ===================
__global__ void gather_finalize_k(const float* __restrict__ oall, const float* __restrict__ w,
                                  float* __restrict__ context, float* __restrict__ inputs,
                                  __half* __restrict__ Xh, int first)
{
    int idx = blockIdx.x * 256 + threadIdx.x;    // NELEM elements
    int h = idx & 255;
    int t = idx >> 8;
    int f = t >> 7;
    int pos = t & 127;

    const int sc[3]   = {2, 4, 6};
    const int Ss[3]   = {256, 512, 768};
    const int ro[3]   = {ROFF0, ROFF1, ROFF2};

    float acc = 0.f;
    #pragma unroll
    for (int si = 0; si < 3; si++) {
        int s = sc[si], S = Ss[si];
        int nw = F - s + 1;
        int wlo = max(0, f - s + 1);
        int whi = min(f, nw - 1);
        float sum = 0.f;
        for (int ww = wlo; ww <= whi; ww++) {
            int r = ro[si] + ww * S + (f - ww) * PP + pos;
            sum += oall[(size_t)r * HH + h];
        }
        acc += sum / (float)(whi - wlo + 1);
    }
    float v = 0.25f * acc;
    float ww = w[f];
    context[idx] = first ? (v * ww) : (v * ww + context[idx] * (1.f - ww));
    inputs[idx] = v;
    Xh[idx] = __float2half(v);
}

// =================== context reduction + classifier ===================
__global__ void ctxpart_k(const float* __restrict__ context, float* __restrict__ partial)
{
    int f = blockIdx.x;
    int h = threadIdx.x;          // 256
    float s = 0.f;
    const float* cp = context + (size_t)f * PP * HH + h;
    #pragma unroll 4
    for (int pos = 0; pos < PP; pos++) s += cp[(size_t)pos * HH];
    partial[f * HH + h] = s;
}

__global__ void classify_k(const float* __restrict__ partial, const float* __restrict__ clsW,
                           const float* __restrict__ clsb, float* __restrict__ out)
{
    __shared__ float cs[HH];
    int tid = threadIdx.x;        // 128
    for (int h = tid; h < HH; h += 128) {
        float s = 0.f;
        #pragma unroll
        for (int f = 0; f < F; f++) s += partial[f * HH + h];
        cs[h] = s;
    }
    __syncthreads();
    int j = blockIdx.x * 128 + tid;
    if (j < NCLS) {
        float acc = clsb[j];
        for (int h = 0; h < HH; h++) acc = fmaf(cs[h], clsW[h * NCLS + j], acc);
        out[j] = acc;
    }
}

// =================== host launch ===================
extern "C" void kernel_launch(void* const* d_in, const int* in_sizes, int n_in,
                              void* d_out, int out_size)
{
    (void)in_sizes; (void)n_in; (void)out_size;
    const float* embed  = (const float*)d_in[0];
    const float* halt_W = (const float*)d_in[3];
    const float* halt_b = (const float*)d_in[4];
    const float* cls_W  = (const float*)d_in[8];
    const float* cls_b  = (const float*)d_in[9];
    const float* Wq = (const float*)d_in[10];
    const float* bq = (const float*)d_in[11];
    const float* Wk = (const float*)d_in[12];
    const float* bk = (const float*)d_in[13];
    const float* Wv = (const float*)d_in[14];
    const float* bv = (const float*)d_in[15];
    const float* Wo = (const float*)d_in[16];
    const float* bo = (const float*)d_in[17];
    float* out = (float*)d_out;

    float *inputs, *oall, *context, *sig, *ptn, *Rt, *w, *partial;
    __half *Xh, *Qh, *Kh, *attnh, *Wqkvh, *Woh;
    uint32_t *Vt;
    cudaGetSymbolAddress((void**)&inputs,  d_inputs);
    cudaGetSymbolAddress((void**)&Xh,      d_Xh);
    cudaGetSymbolAddress((void**)&Qh,      d_Qh);
    cudaGetSymbolAddress((void**)&Kh,      d_Kh);
    cudaGetSymbolAddress((void**)&Vt,      d_Vt);
    cudaGetSymbolAddress((void**)&attnh,   d_attnh);
    cudaGetSymbolAddress((void**)&Wqkvh,   d_Wqkvh);
    cudaGetSymbolAddress((void**)&Woh,     d_Woh);
    cudaGetSymbolAddress((void**)&oall,    d_oall);
    cudaGetSymbolAddress((void**)&context, d_context);
    cudaGetSymbolAddress((void**)&sig,     d_sig);
    cudaGetSymbolAddress((void**)&ptn,     d_ptn);
    cudaGetSymbolAddress((void**)&Rt,      d_Rt);
    cudaGetSymbolAddress((void**)&w,       d_w);
    cudaGetSymbolAddress((void**)&partial, d_partial);

    // weight conversions (once per call)
    {
        dim3 b(32, 8);
        dim3 gq(8, 8, 9);
        convwt_qkv_k<<<gq, b>>>(Wq, Wk, Wv, Wqkvh);
        dim3 go(8, 8, 3);
        convwt_k<<<go, b>>>(Wo, Woh);
    }
    // X fp16 for iter 0
    xconv_k<<<NELEM / 512, 256>>>(embed, Xh);

    for (int iter = 0; iter < 2; iter++) {
        const float* X = (iter == 0) ? embed : inputs;

        // halting: warp-per-2-positions sigmoid dot, then fused mean+ACT
        halt_sig_k<<<TPAIRS / 8, 256>>>(X, halt_W, halt_b, sig);
        act2_k<<<1, 576>>>(sig, ptn, Rt, w, iter == 0 ? 1 : 0);

        // QKV (fp16 tensor GEMM) for all 3 scales; V written transposed (Vt)
        dim3 gq(NTOK / 128, 2, 9);
        gemm_qkv_mma_k<<<gq, 256>>>(Xh, Wqkvh, bq, bk, bv, Qh, Kh, Vt);

        // tensor-core attention, all scales: 172 pairs x 8 heads, 128 q/block
        dim3 ga(172, 8);
        attn_mma_k<<<ga, 256>>>(Qh, Kh, Vt, attnh);

        // O-projection (fp16 tensor GEMM) over all 22016 rows
        dim3 go(TOTROWS / 128, 2);
        gemm_oproj_mma_k<<<go, 256>>>(attnh, Woh, bo, oall);

        // fused gather (all scales) + context/inputs update (+fp16 X for next iter)
        gather_finalize_k<<<NELEM / 256, 256>>>(oall, w, context, inputs, Xh,
                                                iter == 0 ? 1 : 0);
    }
    ctxpart_k<<<F, HH>>>(context, partial);
    classify_k<<<(NCLS + 127) / 128, 128>>>(partial, cls_W, cls_b, out);
}

// round 11
// speedup vs baseline: 1.2056x; 1.2056x over previous
#include <cuda_runtime.h>
#include <cuda_fp16.h>
#include <math.h>
#include <stdint.h>

// Problem constants
#define F 18
#define PP 128
#define HH 256
#define NCLS 625
#define NTOK (F*PP)            // 2304
#define NELEM (F*PP*HH)        // 589824
#define TOTROWS 22016          // 17*256 + 15*512 + 13*768
#define ROFF0 0
#define ROFF1 4352
#define ROFF2 12032
#define TPAIRS 1152            // NTOK/2

// -------- device scratch (allocation-free) --------
__device__ __half d_Xh[NELEM];             // fp16 inputs (for QKV mma)
__device__ __half d_Qh[3*NELEM];
__device__ __half d_Kh[3*NELEM];
__device__ uint32_t d_Vt[3*8*32*TPAIRS];   // [si][h][dim][tokpair] packed half2
__device__ __half d_attnh[TOTROWS*HH];     // attention output (fp16)
__device__ __half d_Wqkvh[9*HH*HH];        // QKV weights transposed [si*3+which][n][k] fp16
__device__ __half d_Woh[3*HH*HH];          // Wo transposed [si][n][k] fp16
__device__ float d_oall[TOTROWS*HH];
__device__ float d_context[NELEM];
__device__ float d_sig[NTOK];
__device__ float d_ptn[F];
__device__ float d_Rt[F];
__device__ float d_w[F];
__device__ float d_partial[F*HH];

__device__ __forceinline__ uint32_t packh2(float a, float b) {
    __half2 h = __floats2half2_rn(a, b);
    return *(uint32_t*)&h;
}

__device__ __forceinline__ uint32_t h2ex2(uint32_t x) {
    uint32_t y;
    asm("ex2.approx.f16x2 %0, %1;" : "=r"(y) : "r"(x));
    return y;
}

__device__ __forceinline__ void cp16(uint32_t saddr, const void* g) {
    asm volatile("cp.async.cg.shared.global [%0], [%1], 16;\n" :: "r"(saddr), "l"(g));
}
#define CP_COMMIT() asm volatile("cp.async.commit_group;\n" ::: "memory")
#define CP_WAIT1()  asm volatile("cp.async.wait_group 1;\n" ::: "memory")
#define CP_WAIT0()  asm volatile("cp.async.wait_group 0;\n" ::: "memory")

// mma.sync m16n8k16 fp16 -> fp32 accumulate in-place
__device__ __forceinline__ void mma_f16(float c[4], const uint32_t a[4],
                                        uint32_t b0, uint32_t b1)
{
    asm volatile(
        "mma.sync.aligned.m16n8k16.row.col.f32.f16.f16.f32 "
        "{%0,%1,%2,%3}, {%4,%5,%6,%7}, {%8,%9}, {%0,%1,%2,%3};\n"
        : "+f"(c[0]), "+f"(c[1]), "+f"(c[2]), "+f"(c[3])
        : "r"(a[0]), "r"(a[1]), "r"(a[2]), "r"(a[3]), "r"(b0), "r"(b1));
}

// =================== halting (iter 0 only): two positions per warp ===================
__global__ void __launch_bounds__(256)
halt_sig_k(const float* __restrict__ x, const float* __restrict__ hW,
           const float* __restrict__ hb, float* __restrict__ sig)
{
    int warp = threadIdx.x >> 5;
    int lane = threadIdx.x & 31;
    int pos = blockIdx.x * 8 + warp;      // [0, 1152); second position = pos + 1152
    const float* xp0 = x + (size_t)pos * HH + lane * 8;
    const float* xp1 = x + (size_t)(pos + TPAIRS) * HH + lane * 8;
    const float* wp = hW + lane * 8;
    float4 a0 = *(const float4*)xp0;
    float4 a1 = *(const float4*)(xp0 + 4);
    float4 b0 = *(const float4*)xp1;
    float4 b1 = *(const float4*)(xp1 + 4);
    float4 w0 = *(const float4*)wp;
    float4 w1 = *(const float4*)(wp + 4);
    float acc0 = a0.x * w0.x + a0.y * w0.y + a0.z * w0.z + a0.w * w0.w
               + a1.x * w1.x + a1.y * w1.y + a1.z * w1.z + a1.w * w1.w;
    float acc1 = b0.x * w0.x + b0.y * w0.y + b0.z * w0.z + b0.w * w0.w
               + b1.x * w1.x + b1.y * w1.y + b1.z * w1.z + b1.w * w1.w;
    #pragma unroll
    for (int off = 16; off > 0; off >>= 1) {
        acc0 += __shfl_xor_sync(0xffffffffu, acc0, off);
        acc1 += __shfl_xor_sync(0xffffffffu, acc1, off);
    }
    if (lane == 0) {
        sig[pos] = 1.f / (1.f + __expf(-(acc0 + hb[0])));
        sig[pos + TPAIRS] = 1.f / (1.f + __expf(-(acc1 + hb[0])));
    }
}

// =================== halting phase 2 (mean) + ACT, one block ===================
__global__ void __launch_bounds__(576)
act2_k(const float* __restrict__ sig, float* __restrict__ ptn,
       float* __restrict__ Rt, float* __restrict__ w, int first)
{
    int f = threadIdx.x >> 5;      // 0..17
    int lane = threadIdx.x & 31;
    const float4 v = *(const float4*)&sig[f * PP + lane * 4];
    float acc = v.x + v.y + v.z + v.w;
    #pragma unroll
    for (int off = 16; off > 0; off >>= 1)
        acc += __shfl_xor_sync(0xffffffffu, acc, off);
    if (lane == 0) {
        float pf = acc * (1.f / 128.f);
        float pt = first ? 0.f : ptn[f];
        float rt = first ? 0.f : Rt[f];
        float run = (pt < 1.0f) ? 1.f : 0.f;
        float t = pt + pf * run;
        float nh   = (t > 0.99f)  ? run : 0.f;
        float run2 = (t <= 0.99f) ? run : 0.f;
        pt = pt + pf * run2;
        rt = rt + nh * (1.f - pt);
        pt = pt + nh * rt;
        ptn[f] = pt; Rt[f] = rt;
        w[f] = pf * run2 + nh * rt;
    }
}

// =================== weight transpose+convert: [k][n] f32 -> [n][k] f16 ===================
__global__ void __launch_bounds__(256)
convwt_k(const float* __restrict__ W, __half* __restrict__ Wt)
{
    __shared__ float t[32][33];
    int z = blockIdx.z;
    int k0 = blockIdx.x * 32, n0 = blockIdx.y * 32;
    int tx = threadIdx.x, ty = threadIdx.y;     // 32 x 8
    const float* src = W + (size_t)z * HH * HH;
    __half* dst = Wt + (size_t)z * HH * HH;
    #pragma unroll
    for (int r = ty; r < 32; r += 8)
        t[r][tx] = src[(size_t)(k0 + r) * HH + n0 + tx];
    __syncthreads();
    #pragma unroll
    for (int r = ty; r < 32; r += 8)
        dst[(size_t)(n0 + r) * HH + k0 + tx] = __float2half(t[tx][r]);
}

__global__ void __launch_bounds__(256)
convwt_qkv_k(const float* __restrict__ Wq, const float* __restrict__ Wk,
             const float* __restrict__ Wv, __half* __restrict__ Wt)
{
    __shared__ float t[32][33];
    int z = blockIdx.z;              // 0..8
    int si = z / 3, which = z - si * 3;
    const float* W = (which == 0) ? Wq : ((which == 1) ? Wk : Wv);
    const float* src = W + (size_t)si * HH * HH;
    __half* dst = Wt + (size_t)z * HH * HH;
    int k0 = blockIdx.x * 32, n0 = blockIdx.y * 32;
    int tx = threadIdx.x, ty = threadIdx.y;
    #pragma unroll
    for (int r = ty; r < 32; r += 8)
        t[r][tx] = src[(size_t)(k0 + r) * HH + n0 + tx];
    __syncthreads();
    #pragma unroll
    for (int r = ty; r < 32; r += 8)
        dst[(size_t)(n0 + r) * HH + k0 + tx] = __float2half(t[tx][r]);
}

// =================== X -> fp16 ===================
__global__ void xconv_k(const float* __restrict__ X, __half* __restrict__ Xh)
{
    int i = blockIdx.x * 256 + threadIdx.x;
    float2 v = *(const float2*)&X[2 * i];
    *(uint32_t*)&Xh[2 * i] = packh2(v.x, v.y);
}

// =================== fp16 mma GEMM mainloop, tile 128x128, K=256 ===================
// cp.async 2-stage pipeline. sbuf: 4 buffers of 128*OSTRIDE uint32:
// [As0][Bs0][As1][Bs1].
#define OSTRIDE 36
#define GBUF (128 * OSTRIDE)
__device__ __forceinline__ void mma_mainloop(const __half* __restrict__ A, int bm,
                                             const __half* __restrict__ Bw, int bn,
                                             uint32_t* sbuf, float acc[2][8][4])
{
    const int tid  = threadIdx.x;
    const int warp = tid >> 5;
    const int lane = tid & 31;
    const int gid  = lane >> 2;
    const int tig  = lane & 3;
    const int wm = (warp & 3) * 32;
    const int wn = (warp >> 2) * 64;
    const uint32_t sb = (uint32_t)__cvta_generic_to_shared(sbuf);

    #pragma unroll
    for (int mt = 0; mt < 2; mt++)
        #pragma unroll
        for (int nt = 0; nt < 8; nt++)
            #pragma unroll
            for (int i = 0; i < 4; i++) acc[mt][nt][i] = 0.f;

    // issue loads for k-chunk kc into stage st
    auto issue = [&](int kc, int st) {
        uint32_t aoff = sb + (uint32_t)(2 * st) * (GBUF * 4);
        uint32_t boff = aoff + GBUF * 4;
        for (int i = tid; i < 1024; i += 256) {
            int m = i >> 3, q = i & 7;
            uint32_t so = (uint32_t)(m * OSTRIDE + q * 4) * 4;
            cp16(aoff + so, &A[(size_t)(bm + m) * 256 + kc + q * 8]);
            cp16(boff + so, &Bw[(size_t)(bn + m) * 256 + kc + q * 8]);
        }
        CP_COMMIT();
    };

    issue(0, 0);
    #pragma unroll
    for (int kci = 0; kci < 4; kci++) {
        if (kci < 3) issue((kci + 1) * 64, (kci + 1) & 1);
        if (kci < 3) CP_WAIT1(); else CP_WAIT0();
        __syncthreads();
        uint32_t* As = sbuf + 2 * (kci & 1) * GBUF;
        uint32_t* Bs = As + GBUF;
        #pragma unroll
        for (int ks = 0; ks < 4; ks++) {
            uint32_t a[2][4];
            #pragma unroll
            for (int mt = 0; mt < 2; mt++) {
                int r0 = (wm + mt * 16 + gid) * OSTRIDE + ks * 8;
                int r1 = (wm + mt * 16 + gid + 8) * OSTRIDE + ks * 8;
                a[mt][0] = As[r0 + tig];
                a[mt][1] = As[r1 + tig];
                a[mt][2] = As[r0 + tig + 4];
                a[mt][3] = As[r1 + tig + 4];
            }
            #pragma unroll
            for (int nt = 0; nt < 8; nt++) {
                int nr = (wn + nt * 8 + gid) * OSTRIDE + ks * 8;
                uint32_t b0 = Bs[nr + tig];
                uint32_t b1 = Bs[nr + tig + 4];
                #pragma unroll
                for (int mt = 0; mt < 2; mt++)
                    mma_f16(acc[mt][nt], a[mt], b0, b1);
            }
        }
        __syncthreads();   // guard stage before next issue overwrites it
    }
}

// QKV mma GEMM: grid (18, 2, 9); z: si=z/3, which=z%3.
__global__ void __launch_bounds__(256)
gemm_qkv_mma_k(const __half* __restrict__ Xh, const __half* __restrict__ Wt,
               const float* __restrict__ bq, const float* __restrict__ bk,
               const float* __restrict__ bv,
               __half* __restrict__ Q, __half* __restrict__ K,
               uint32_t* __restrict__ Vt)
{
    __shared__ uint32_t sbuf[4 * GBUF];
    int z = blockIdx.z;
    int si = z / 3, which = z - si * 3;
    int bm = blockIdx.x * 128, bn = blockIdx.y * 128;

    float acc[2][8][4];
    mma_mainloop(Xh, bm, Wt + (size_t)z * HH * HH, bn, sbuf, acc);

    const int tid  = threadIdx.x;
    const int warp = tid >> 5;
    const int lane = tid & 31;
    const int gid  = lane >> 2;
    const int tig  = lane & 3;
    const int wm = (warp & 3) * 32;
    const int wn = (warp >> 2) * 64;

    if (which < 2) {
        const float* bias = ((which == 0) ? bq : bk) + si * HH;
        __half* C = ((which == 0) ? Q : K) + (size_t)si * NELEM;
        float oscale = (which == 0) ? (0.17677669529663687f * 1.4426950408889634f) : 1.0f;
        #pragma unroll
        for (int nt = 0; nt < 8; nt++) {
            int n = bn + wn + nt * 8 + 2 * tig;
            float b0 = bias[n], b1 = bias[n + 1];
            #pragma unroll
            for (int mt = 0; mt < 2; mt++) {
                int m = bm + wm + mt * 16 + gid;
                *(uint32_t*)&C[(size_t)m * 256 + n] =
                    packh2((acc[mt][nt][0] + b0) * oscale, (acc[mt][nt][1] + b1) * oscale);
                *(uint32_t*)&C[(size_t)(m + 8) * 256 + n] =
                    packh2((acc[mt][nt][2] + b0) * oscale, (acc[mt][nt][3] + b1) * oscale);
            }
        }
    } else {
        // stage fp16 tile [tok][dim] in smem, then write transposed packed Vt
        const float* bias = bv + si * HH;
        __half* stag = (__half*)sbuf;            // [128 tok][stride 130]
        __syncthreads();                          // mainloop smem reads done
        #pragma unroll
        for (int nt = 0; nt < 8; nt++) {
            int nl = wn + nt * 8 + 2 * tig;
            float b0 = bias[bn + nl], b1 = bias[bn + nl + 1];
            #pragma unroll
            for (int mt = 0; mt < 2; mt++) {
                int ml = wm + mt * 16 + gid;
                *(uint32_t*)&stag[ml * 130 + nl] =
                    packh2(acc[mt][nt][0] + b0, acc[mt][nt][1] + b1);
                *(uint32_t*)&stag[(ml + 8) * 130 + nl] =
                    packh2(acc[mt][nt][2] + b0, acc[mt][nt][3] + b1);
            }
        }
        __syncthreads();
        const int tpg0 = bm >> 1;
        uint32_t* vtb = Vt + (size_t)si * 8 * 32 * TPAIRS;
        #pragma unroll
        for (int j = tid; j < 8192; j += 256) {
            int tp = j & 63;          // local token pair
            int nl = j >> 6;          // local dim col 0..127
            int ncol = bn + nl;
            int h = ncol >> 5, d = ncol & 31;
            __half lo = stag[(2 * tp) * 130 + nl];
            __half hi = stag[(2 * tp + 1) * 130 + nl];
            __half2 pr = __halves2half2(lo, hi);
            vtb[((size_t)(h * 32 + d)) * TPAIRS + tpg0 + tp] = *(uint32_t*)&pr;
        }
    }
}

// O-projection mma GEMM: grid (172, 2)
__global__ void __launch_bounds__(256)
gemm_oproj_mma_k(const __half* __restrict__ A, const __half* __restrict__ Wt,
                 const float* __restrict__ bo, float* __restrict__ C)
{
    __shared__ uint32_t sbuf[4 * GBUF];
    int bm = blockIdx.x * 128, bn = blockIdx.y * 128;
    int si = (bm >= ROFF2) ? 2 : ((bm >= ROFF1) ? 1 : 0);

    float acc[2][8][4];
    mma_mainloop(A, bm, Wt + (size_t)si * HH * HH, bn, sbuf, acc);

    const int tid  = threadIdx.x;
    const int warp = tid >> 5;
    const int lane = tid & 31;
    const int gid  = lane >> 2;
    const int tig  = lane & 3;
    const int wm = (warp & 3) * 32;
    const int wn = (warp >> 2) * 64;
    const float* bias = bo + si * HH;

    #pragma unroll
    for (int nt = 0; nt < 8; nt++) {
        int n = bn + wn + nt * 8 + 2 * tig;
        float b0 = bias[n], b1 = bias[n + 1];
        #pragma unroll
        for (int mt = 0; mt < 2; mt++) {
            int m = bm + wm + mt * 16 + gid;
            *(float2*)&C[(size_t)m * 256 + n] =
                make_float2(acc[mt][nt][0] + b0, acc[mt][nt][1] + b1);
            *(float2*)&C[(size_t)(m + 8) * 256 + n] =
                make_float2(acc[mt][nt][2] + b0, acc[mt][nt][3] + b1);
        }
    }
}

// =================== tensor-core flash attention, hd=32, all fp16 mma ===================
// cp.async 2-stage pipeline on K/V tiles; longest windows (s=6) scheduled first.
// block = 256 threads (8 warps) = 128 queries of one (scale, window, head).
#define KPSTRIDE 36
#define VTSTRIDE 36
__global__ void __launch_bounds__(256, 3)
attn_mma_k(const __half* __restrict__ Qg, const __half* __restrict__ Kg,
           const uint32_t* __restrict__ Vt, __half* __restrict__ O)
{
    __shared__ uint32_t Kp[2][64 * KPSTRIDE];   // [stage][key][kpair]
    __shared__ uint32_t Vs[2][32 * VTSTRIDE];   // [stage][dim][keypair]

    const int tid  = threadIdx.x;
    const int warp = tid >> 5;
    const int lane = tid & 31;
    const int gid  = lane >> 2;
    const int tig  = lane & 3;
    const int h    = blockIdx.y;

    int pid = blockIdx.x;
    int si, S, w, j0, rowoff;
    if (pid < 78)       { si = 2; S = 768; w = pid / 6;  j0 = (pid - w * 6) << 7; rowoff = ROFF2; }
    else if (pid < 138) { pid -= 78;  si = 1; S = 512; w = pid >> 2; j0 = (pid & 3) << 7; rowoff = ROFF1; }
    else                { pid -= 138; si = 0; S = 256; w = pid >> 1; j0 = (pid & 1) << 7; rowoff = ROFF0; }

    const __half* Q = Qg + (size_t)si * NELEM;
    const __half* K = Kg + (size_t)si * NELEM;
    const uint32_t* Vtb = Vt + ((size_t)si * 8 + h) * 32 * TPAIRS;

    const uint32_t kpb = (uint32_t)__cvta_generic_to_shared(&Kp[0][0]);
    const uint32_t vsb = (uint32_t)__cvta_generic_to_shared(&Vs[0][0]);

    // issue K/V tile at key offset kb into stage st (one cp16 per thread per tensor)
    auto issueKV = [&](int kb, int st) {
        {
            const __half* kg = K + ((size_t)(w * PP + kb)) * HH + h * 32;
            int key = tid >> 2, q = tid & 3;
            cp16(kpb + (uint32_t)(st * 64 * KPSTRIDE + key * KPSTRIDE + q * 4) * 4,
                 kg + (size_t)key * HH + q * 8);
        }
        {
            const uint32_t* vg = Vtb + ((w * PP + kb) >> 1);
            int d = tid >> 3, q = tid & 7;
            cp16(vsb + (uint32_t)(st * 32 * VTSTRIDE + d * VTSTRIDE + q * 4) * 4,
                 vg + (size_t)d * TPAIRS + q * 4);
        }
        CP_COMMIT();
    };

    const int qrow = w * PP + j0 + warp * 16 + gid;
    uint32_t qa[2][4];
    #pragma unroll
    for (int ks = 0; ks < 2; ks++) {
        const uint32_t* q0 = (const uint32_t*)(Q + (size_t)qrow * HH + h * 32 + ks * 16);
        const uint32_t* q1 = (const uint32_t*)(Q + (size_t)(qrow + 8) * HH + h * 32 + ks * 16);
        qa[ks][0] = q0[tig];
        qa[ks][1] = q1[tig];
        qa[ks][2] = q0[tig + 4];
        qa[ks][3] = q1[tig + 4];
    }

    float o[4][4];
    #pragma unroll
    for (int v = 0; v < 4; v++)
        #pragma unroll
        for (int i = 0; i < 4; i++) o[v][i] = 0.f;
    float l0 = 0.f, l1 = 0.f;

    issueKV(0, 0);
    for (int kb = 0; kb < S; kb += 64) {
        const int st = (kb >> 6) & 1;
        const bool more = (kb + 64) < S;
        if (more) issueKV(kb + 64, st ^ 1);
        if (more) CP_WAIT1(); else CP_WAIT0();
        __syncthreads();

        float s[8][4];
        #pragma unroll
        for (int t = 0; t < 8; t++) {
            s[t][0] = s[t][1] = s[t][2] = s[t][3] = 0.f;
            const int krow = (8 * t + gid) * KPSTRIDE;
            #pragma unroll
            for (int ks = 0; ks < 2; ks++) {
                uint32_t b0 = Kp[st][krow + ks * 8 + tig];
                uint32_t b1 = Kp[st][krow + ks * 8 + tig + 4];
                mma_f16(s[t], qa[ks], b0, b1);
            }
        }

        // pack logits to fp16, exponentiate in fp16 (log2 domain), sum in fp32
        uint32_t e0[8], e1[8];
        #pragma unroll
        for (int t = 0; t < 8; t++) {
            e0[t] = h2ex2(packh2(s[t][0], s[t][1]));   // row gid
            e1[t] = h2ex2(packh2(s[t][2], s[t][3]));   // row gid+8
            float2 f0 = __half22float2(*(__half2*)&e0[t]);
            float2 f1 = __half22float2(*(__half2*)&e1[t]);
            l0 += f0.x + f0.y;
            l1 += f1.x + f1.y;
        }

        #pragma unroll
        for (int u = 0; u < 4; u++) {
            uint32_t pa[4];
            pa[0] = e0[2*u];
            pa[1] = e1[2*u];
            pa[2] = e0[2*u+1];
            pa[3] = e1[2*u+1];
            #pragma unroll
            for (int v = 0; v < 4; v++) {
                uint32_t b0 = Vs[st][(gid + 8 * v) * VTSTRIDE + 8 * u + tig];
                uint32_t b1 = Vs[st][(gid + 8 * v) * VTSTRIDE + 8 * u + tig + 4];
                mma_f16(o[v], pa, b0, b1);
            }
        }
        __syncthreads();   // guard stage before next issue overwrites it
    }

    l0 += __shfl_xor_sync(0xffffffffu, l0, 1);
    l0 += __shfl_xor_sync(0xffffffffu, l0, 2);
    l1 += __shfl_xor_sync(0xffffffffu, l1, 1);
    l1 += __shfl_xor_sync(0xffffffffu, l1, 2);
    float il0 = 1.f / l0, il1 = 1.f / l1;

    const int orow = rowoff + w * S + j0 + warp * 16 + gid;
    #pragma unroll
    for (int v = 0; v < 4; v++) {
        *(uint32_t*)&O[(size_t)orow * HH + h * 32 + v * 8 + 2 * tig] =
            packh2(o[v][0] * il0, o[v][1] * il0);
        *(uint32_t*)&O[(size_t)(orow + 8) * HH + h * 32 + v * 8 + 2 * tig] =
            packh2(o[v][2] * il1, o[v][3] * il1);
    }
}

// =================== fused overlap-add gather + finalize + next-iter halt ===================
// Block = one token (256 dims). Computes new input v, context update, fp16 X,
// AND the halting sigmoid for the NEXT iteration (block dot with halt_W).
__global__ void gather_finalize_k(const float* __restrict__ oall, const float* __restrict__ w,
                                  float* __restrict__ context, __half* __restrict__ Xh,
                                  const float* __restrict__ hW, const float* __restrict__ hb,
                                  float* __restrict__ sig, int first)
{
    int idx = blockIdx.x * 256 + threadIdx.x;    // NELEM elements
    int h = threadIdx.x;                          // dim
    int t = blockIdx.x;                           // token
    int f = t >> 7;
    int pos = t & 127;

    const int sc[3]   = {2, 4, 6};
    const int Ss[3]   = {256, 512, 768};
    const int ro[3]   = {ROFF0, ROFF1, ROFF2};

    float acc = 0.f;
    #pragma unroll
    for (int si = 0; si < 3; si++) {
        int s = sc[si], S = Ss[si];
        int nw = F - s + 1;
        int wlo = max(0, f - s + 1);
        int whi = min(f, nw - 1);
        float sum = 0.f;
        for (int ww = wlo; ww <= whi; ww++) {
            int r = ro[si] + ww * S + (f - ww) * PP + pos;
            sum += oall[(size_t)r * HH + h];
        }
        acc += sum / (float)(whi - wlo + 1);
    }
    float v = 0.25f * acc;
    float ww = w[f];
    context[idx] = first ? (v * ww) : (v * ww + context[idx] * (1.f - ww));
    Xh[idx] = __float2half(v);
    (void)pos;

    // halting dot for next iteration: sig[t] = sigmoid(sum_h v*hW[h] + hb)
    float prod = v * hW[h];
    #pragma unroll
    for (int off = 16; off > 0; off >>= 1)
        prod += __shfl_xor_sync(0xffffffffu, prod, off);
    __shared__ float red[8];
    if ((threadIdx.x & 31) == 0) red[threadIdx.x >> 5] = prod;
    __syncthreads();
    if (threadIdx.x == 0) {
        float s = red[0] + red[1] + red[2] + red[3] + red[4] + red[5] + red[6] + red[7];
        sig[t] = 1.f / (1.f + __expf(-(s + hb[0])));
    }
}

// =================== context reduction + classifier ===================
__global__ void ctxpart_k(const float* __restrict__ context, float* __restrict__ partial)
{
    int f = blockIdx.x;
    int h = threadIdx.x;          // 256
    float s = 0.f;
    const float* cp = context + (size_t)f * PP * HH + h;
    #pragma unroll 4
    for (int pos = 0; pos < PP; pos++) s += cp[(size_t)pos * HH];
    partial[f * HH + h] = s;
}

__global__ void classify_k(const float* __restrict__ partial, const float* __restrict__ clsW,
                           const float* __restrict__ clsb, float* __restrict__ out)
{
    __shared__ float cs[HH];
    int tid = threadIdx.x;        // 128
    for (int h = tid; h < HH; h += 128) {
        float s = 0.f;
        #pragma unroll
        for (int f = 0; f < F; f++) s += partial[f * HH + h];
        cs[h] = s;
    }
    __syncthreads();
    int j = blockIdx.x * 128 + tid;
    if (j < NCLS) {
        float acc = clsb[j];
        for (int h = 0; h < HH; h++) acc = fmaf(cs[h], clsW[h * NCLS + j], acc);
        out[j] = acc;
    }
}

// =================== host launch ===================
extern "C" void kernel_launch(void* const* d_in, const int* in_sizes, int n_in,
                              void* d_out, int out_size)
{
    (void)in_sizes; (void)n_in; (void)out_size;
    const float* embed  = (const float*)d_in[0];
    const float* halt_W = (const float*)d_in[3];
    const float* halt_b = (const float*)d_in[4];
    const float* cls_W  = (const float*)d_in[8];
    const float* cls_b  = (const float*)d_in[9];
    const float* Wq = (const float*)d_in[10];
    const float* bq = (const float*)d_in[11];
    const float* Wk = (const float*)d_in[12];
    const float* bk = (const float*)d_in[13];
    const float* Wv = (const float*)d_in[14];
    const float* bv = (const float*)d_in[15];
    const float* Wo = (const float*)d_in[16];
    const float* bo = (const float*)d_in[17];
    float* out = (float*)d_out;

    float *oall, *context, *sig, *ptn, *Rt, *w, *partial;
    __half *Xh, *Qh, *Kh, *attnh, *Wqkvh, *Woh;
    uint32_t *Vt;
    cudaGetSymbolAddress((void**)&Xh,      d_Xh);
    cudaGetSymbolAddress((void**)&Qh,      d_Qh);
    cudaGetSymbolAddress((void**)&Kh,      d_Kh);
    cudaGetSymbolAddress((void**)&Vt,      d_Vt);
    cudaGetSymbolAddress((void**)&attnh,   d_attnh);
    cudaGetSymbolAddress((void**)&Wqkvh,   d_Wqkvh);
    cudaGetSymbolAddress((void**)&Woh,     d_Woh);
    cudaGetSymbolAddress((void**)&oall,    d_oall);
    cudaGetSymbolAddress((void**)&context, d_context);
    cudaGetSymbolAddress((void**)&sig,     d_sig);
    cudaGetSymbolAddress((void**)&ptn,     d_ptn);
    cudaGetSymbolAddress((void**)&Rt,      d_Rt);
    cudaGetSymbolAddress((void**)&w,       d_w);
    cudaGetSymbolAddress((void**)&partial, d_partial);

    // weight conversions (once per call)
    {
        dim3 b(32, 8);
        dim3 gq(8, 8, 9);
        convwt_qkv_k<<<gq, b>>>(Wq, Wk, Wv, Wqkvh);
        dim3 go(8, 8, 3);
        convwt_k<<<go, b>>>(Wo, Woh);
    }
    // X fp16 for iter 0
    xconv_k<<<NELEM / 512, 256>>>(embed, Xh);
    // halting sigmoid for iter 0 (iter 1's is fused into gather_finalize)
    halt_sig_k<<<TPAIRS / 8, 256>>>(embed, halt_W, halt_b, sig);

    for (int iter = 0; iter < 2; iter++) {
        act2_k<<<1, 576>>>(sig, ptn, Rt, w, iter == 0 ? 1 : 0);

        // QKV (fp16 tensor GEMM) for all 3 scales; V written transposed (Vt)
        dim3 gq(NTOK / 128, 2, 9);
        gemm_qkv_mma_k<<<gq, 256>>>(Xh, Wqkvh, bq, bk, bv, Qh, Kh, Vt);

        // tensor-core attention, all scales: 172 pairs x 8 heads, 128 q/block
        dim3 ga(172, 8);
        attn_mma_k<<<ga, 256>>>(Qh, Kh, Vt, attnh);

        // O-projection (fp16 tensor GEMM) over all 22016 rows
        dim3 go(TOTROWS / 128, 2);
        gemm_oproj_mma_k<<<go, 256>>>(attnh, Woh, bo, oall);

        // fused gather + context update + fp16 X + next-iter halting sigmoid
        gather_finalize_k<<<NELEM / 256, 256>>>(oall, w, context, Xh,
                                                halt_W, halt_b, sig,
                                                iter == 0 ? 1 : 0);
    }
    ctxpart_k<<<F, HH>>>(context, partial);
    classify_k<<<(NCLS + 127) / 128, 128>>>(partial, cls_W, cls_b, out);
}